// round 1
// baseline (speedup 1.0000x reference)
#include <cuda_runtime.h>
#include <math.h>

#define BATCH_MAX 2048

// ---------------- scratch (device globals; no allocation) ----------------
__device__ float4 g_fcwT[8192];          // fc_w transposed: [idx][k]
__device__ float4 g_A[16 * 1024];        // folded fc2+dconv1 weights: [oc*1024+px][k]
__device__ float  g_Beff[16 * 1024];     // folded bias
__device__ float  g_ang[BATCH_MAX * 4];  // angles out of frontend
__device__ float  g_q[BATCH_MAX * 4];    // quantum expvals

// ---------------- prep: fc_w transpose + fc2/dconv1 fold ----------------
__global__ void prep_kernel(const float* __restrict__ fc_w,      // (4,8192)
                            const float* __restrict__ fc2_w,     // (8192,4)
                            const float* __restrict__ fc2_b,     // (8192)
                            const float* __restrict__ dconv1_w,  // (16,8,3,3)
                            const float* __restrict__ dconv1_b)  // (16)
{
    int i = blockIdx.x * blockDim.x + threadIdx.x;
    if (i < 8192) {
        g_fcwT[i] = make_float4(fc_w[i], fc_w[8192 + i], fc_w[16384 + i], fc_w[24576 + i]);
    }
    if (i < 16 * 1024) {
        int oc = i >> 10, px = i & 1023, y = px >> 5, x = px & 31;
        float s0 = 0.f, s1 = 0.f, s2 = 0.f, s3 = 0.f;
        float bs = dconv1_b[oc];
        for (int c = 0; c < 8; c++) {
            for (int dy = 0; dy < 3; dy++) {
                int iy = y + dy - 1;
                if ((unsigned)iy >= 32u) continue;
                for (int dx = 0; dx < 3; dx++) {
                    int ix = x + dx - 1;
                    if ((unsigned)ix >= 32u) continue;
                    int idx = (c << 10) + (iy << 5) + ix;
                    float w = dconv1_w[((oc * 8 + c) * 3 + dy) * 3 + dx];
                    float4 f = reinterpret_cast<const float4*>(fc2_w)[idx];
                    s0 = fmaf(w, f.x, s0);
                    s1 = fmaf(w, f.y, s1);
                    s2 = fmaf(w, f.z, s2);
                    s3 = fmaf(w, f.w, s3);
                    bs = fmaf(w, fc2_b[idx], bs);
                }
            }
        }
        g_A[i] = make_float4(s0, s1, s2, s3);
        g_Beff[i] = bs;
    }
}

// ---------------- frontend: conv1+relu -> conv2+relu -> fc (angles) ----------------
struct FrontSmem {
    float sx[3][34][34];     // zero-padded input image
    float sh1[16][34][34];   // zero-padded conv1 output
    float sw1[432];          // conv1_w (16,3,3,3)
    float sw2[1152];         // conv2_w (8,16,3,3)
    float sb1[16];
    float sb2[8];
    float red[8][4];
};

__global__ __launch_bounds__(256, 2) void frontend_kernel(
    const float* __restrict__ x,
    const float* __restrict__ w1, const float* __restrict__ b1,
    const float* __restrict__ w2, const float* __restrict__ b2,
    const float* __restrict__ fcb)
{
    extern __shared__ char raw[];
    FrontSmem& S = *reinterpret_cast<FrontSmem*>(raw);
    const int bidx = blockIdx.x, t = threadIdx.x;

    for (int i = t; i < 3 * 34 * 34; i += 256) ((float*)S.sx)[i] = 0.f;
    for (int i = t; i < 16 * 34 * 34; i += 256) ((float*)S.sh1)[i] = 0.f;
    for (int i = t; i < 432; i += 256) S.sw1[i] = w1[i];
    for (int i = t; i < 1152; i += 256) S.sw2[i] = w2[i];
    if (t < 16) S.sb1[t] = b1[t];
    if (t < 8)  S.sb2[t] = b2[t];
    __syncthreads();

    const float* xb = x + bidx * 3072;
    for (int i = t; i < 3072; i += 256) {
        int c = i >> 10, p = i & 1023;
        S.sx[c][1 + (p >> 5)][1 + (p & 31)] = xb[i];
    }
    __syncthreads();

    const int xc = t & 31, y0 = t >> 5;  // thread owns column xc, rows y0+{0,8,16,24}

    // ---- conv1 (two oc-groups of 8 to bound registers) ----
    for (int g = 0; g < 2; g++) {
        float acc[4][8];
        #pragma unroll
        for (int p = 0; p < 4; p++)
            #pragma unroll
            for (int o = 0; o < 8; o++) acc[p][o] = S.sb1[g * 8 + o];

        #pragma unroll
        for (int ic = 0; ic < 3; ic++)
            #pragma unroll
            for (int dy = 0; dy < 3; dy++)
                #pragma unroll
                for (int dx = 0; dx < 3; dx++) {
                    float a0 = S.sx[ic][y0 + dy][xc + dx];
                    float a1 = S.sx[ic][y0 + 8 + dy][xc + dx];
                    float a2 = S.sx[ic][y0 + 16 + dy][xc + dx];
                    float a3 = S.sx[ic][y0 + 24 + dy][xc + dx];
                    #pragma unroll
                    for (int o = 0; o < 8; o++) {
                        float w = S.sw1[(((g * 8 + o) * 3 + ic) * 3 + dy) * 3 + dx];
                        acc[0][o] = fmaf(a0, w, acc[0][o]);
                        acc[1][o] = fmaf(a1, w, acc[1][o]);
                        acc[2][o] = fmaf(a2, w, acc[2][o]);
                        acc[3][o] = fmaf(a3, w, acc[3][o]);
                    }
                }
        #pragma unroll
        for (int p = 0; p < 4; p++) {
            int y = y0 + p * 8;
            #pragma unroll
            for (int o = 0; o < 8; o++)
                S.sh1[g * 8 + o][1 + y][1 + xc] = fmaxf(acc[p][o], 0.f);
        }
    }
    __syncthreads();

    // ---- conv2 + inline fc accumulation ----
    float acc2[4][8];
    #pragma unroll
    for (int p = 0; p < 4; p++)
        #pragma unroll
        for (int o = 0; o < 8; o++) acc2[p][o] = S.sb2[o];

    #pragma unroll
    for (int ic = 0; ic < 16; ic++)
        #pragma unroll
        for (int dy = 0; dy < 3; dy++)
            #pragma unroll
            for (int dx = 0; dx < 3; dx++) {
                float a0 = S.sh1[ic][y0 + dy][xc + dx];
                float a1 = S.sh1[ic][y0 + 8 + dy][xc + dx];
                float a2 = S.sh1[ic][y0 + 16 + dy][xc + dx];
                float a3 = S.sh1[ic][y0 + 24 + dy][xc + dx];
                #pragma unroll
                for (int o = 0; o < 8; o++) {
                    float w = S.sw2[((o * 16 + ic) * 3 + dy) * 3 + dx];
                    acc2[0][o] = fmaf(a0, w, acc2[0][o]);
                    acc2[1][o] = fmaf(a1, w, acc2[1][o]);
                    acc2[2][o] = fmaf(a2, w, acc2[2][o]);
                    acc2[3][o] = fmaf(a3, w, acc2[3][o]);
                }
            }

    float angk[4] = {0.f, 0.f, 0.f, 0.f};
    #pragma unroll
    for (int p = 0; p < 4; p++) {
        int y = y0 + p * 8;
        #pragma unroll
        for (int o = 0; o < 8; o++) {
            float v = fmaxf(acc2[p][o], 0.f);
            float4 f = g_fcwT[(o << 10) + (y << 5) + xc];
            angk[0] = fmaf(v, f.x, angk[0]);
            angk[1] = fmaf(v, f.y, angk[1]);
            angk[2] = fmaf(v, f.z, angk[2]);
            angk[3] = fmaf(v, f.w, angk[3]);
        }
    }

    // block reduce (deterministic tree)
    #pragma unroll
    for (int k = 0; k < 4; k++)
        #pragma unroll
        for (int off = 16; off > 0; off >>= 1)
            angk[k] += __shfl_xor_sync(0xffffffffu, angk[k], off);
    const int wrp = t >> 5, ln = t & 31;
    if (ln == 0) {
        #pragma unroll
        for (int k = 0; k < 4; k++) S.red[wrp][k] = angk[k];
    }
    __syncthreads();
    if (t < 4) {
        float s = 0.f;
        #pragma unroll
        for (int w = 0; w < 8; w++) s += S.red[w][t];
        g_ang[bidx * 4 + t] = s + fcb[t];
    }
}

// ---------------- quantum: 1 thread = 1 batch element, 16 amps in regs ----------------
__global__ void quantum_kernel(const float* __restrict__ qw, int batch)
{
    int b = blockIdx.x * blockDim.x + threadIdx.x;
    if (b >= batch) return;

    float sr[16], si[16];
    #pragma unroll
    for (int i = 0; i < 16; i++) { sr[i] = 0.f; si[i] = 0.f; }
    sr[0] = 1.f;

    // AngleEmbedding: RX(angle[w]) on wire w   (wire w <-> bit (3-w))
    #pragma unroll
    for (int w = 0; w < 4; w++) {
        float h = 0.5f * g_ang[b * 4 + w];
        float c = cosf(h), s = sinf(h);
        const int bit = 1 << (3 - w);
        #pragma unroll
        for (int i = 0; i < 16; i++) {
            if (i & bit) continue;
            int j = i | bit;
            float ar = sr[i], ai = si[i], br = sr[j], bi = si[j];
            sr[i] = fmaf(c, ar,  s * bi);  si[i] = fmaf(c, ai, -s * br);
            sr[j] = fmaf(c, br,  s * ai);  si[j] = fmaf(c, bi, -s * ar);
        }
    }

    // StronglyEntanglingLayers
    #pragma unroll
    for (int l = 0; l < 3; l++) {
        #pragma unroll
        for (int w = 0; w < 4; w++) {
            float phi = qw[(l * 4 + w) * 3 + 0];
            float th  = qw[(l * 4 + w) * 3 + 1];
            float om  = qw[(l * 4 + w) * 3 + 2];
            float ct = cosf(0.5f * th), st = sinf(0.5f * th);
            float a = 0.5f * (phi + om), d = 0.5f * (phi - om);
            float ca = cosf(a), sa = sinf(a), cd = cosf(d), sd = sinf(d);
            float u00r =  ca * ct, u00i = -sa * ct;
            float u01r = -cd * st, u01i = -sd * st;
            float u10r =  cd * st, u10i = -sd * st;
            float u11r =  ca * ct, u11i =  sa * ct;
            const int bit = 1 << (3 - w);
            #pragma unroll
            for (int i = 0; i < 16; i++) {
                if (i & bit) continue;
                int j = i | bit;
                float ar = sr[i], ai = si[i], br = sr[j], bi = si[j];
                sr[i] = u00r * ar - u00i * ai + u01r * br - u01i * bi;
                si[i] = u00r * ai + u00i * ar + u01r * bi + u01i * br;
                sr[j] = u10r * ar - u10i * ai + u11r * br - u11i * bi;
                si[j] = u10r * ai + u10i * ar + u11r * bi + u11i * br;
            }
        }
        const int r = (l % 3) + 1;
        #pragma unroll
        for (int w = 0; w < 4; w++) {
            int tq = (w + r) & 3;
            const int cb = 1 << (3 - w), tb = 1 << (3 - tq);
            #pragma unroll
            for (int i = 0; i < 16; i++) {
                if ((i & cb) && !(i & tb)) {
                    int j = i | tb;
                    float tr = sr[i]; sr[i] = sr[j]; sr[j] = tr;
                    float ti = si[i]; si[i] = si[j]; si[j] = ti;
                }
            }
        }
    }

    // PauliZ expvals
    #pragma unroll
    for (int w = 0; w < 4; w++) {
        const int bit = 1 << (3 - w);
        float e = 0.f;
        #pragma unroll
        for (int i = 0; i < 16; i++) {
            float p = sr[i] * sr[i] + si[i] * si[i];
            e += (i & bit) ? -p : p;
        }
        g_q[b * 4 + w] = e;
    }
}

// ---------------- backend: (fc2+dconv1 folded)+relu -> dconv2 + sigmoid ----------------
struct BackSmem {
    float sact[16][34][34];  // zero-padded dconv1 output
    float sw[432];           // dconv2_w (3,16,3,3)
    float sb[3];
};

__global__ __launch_bounds__(256, 2) void backend_kernel(
    const float* __restrict__ w2, const float* __restrict__ b2,
    float* __restrict__ out)
{
    extern __shared__ char raw[];
    BackSmem& S = *reinterpret_cast<BackSmem*>(raw);
    const int bidx = blockIdx.x, t = threadIdx.x;

    for (int i = t; i < 16 * 34 * 34; i += 256) ((float*)S.sact)[i] = 0.f;
    for (int i = t; i < 432; i += 256) S.sw[i] = w2[i];
    if (t < 3) S.sb[t] = b2[t];

    const float q0 = g_q[bidx * 4 + 0];
    const float q1 = g_q[bidx * 4 + 1];
    const float q2 = g_q[bidx * 4 + 2];
    const float q3 = g_q[bidx * 4 + 3];
    __syncthreads();

    const int xc = t & 31, y0 = t >> 5;

    // stage 1: dconv1 output via folded weights (4 FMA / element)
    #pragma unroll
    for (int p = 0; p < 4; p++) {
        int y = y0 + p * 8, px = (y << 5) + xc;
        #pragma unroll
        for (int o = 0; o < 16; o++) {
            float4 a = g_A[(o << 10) + px];
            float v = g_Beff[(o << 10) + px];
            v = fmaf(q0, a.x, v);
            v = fmaf(q1, a.y, v);
            v = fmaf(q2, a.z, v);
            v = fmaf(q3, a.w, v);
            S.sact[o][1 + y][1 + xc] = fmaxf(v, 0.f);
        }
    }
    __syncthreads();

    // stage 2: dconv2 + sigmoid
    float acc[4][3];
    #pragma unroll
    for (int p = 0; p < 4; p++)
        #pragma unroll
        for (int o = 0; o < 3; o++) acc[p][o] = S.sb[o];

    #pragma unroll
    for (int ic = 0; ic < 16; ic++)
        #pragma unroll
        for (int dy = 0; dy < 3; dy++)
            #pragma unroll
            for (int dx = 0; dx < 3; dx++) {
                float a0 = S.sact[ic][y0 + dy][xc + dx];
                float a1 = S.sact[ic][y0 + 8 + dy][xc + dx];
                float a2 = S.sact[ic][y0 + 16 + dy][xc + dx];
                float a3 = S.sact[ic][y0 + 24 + dy][xc + dx];
                #pragma unroll
                for (int o = 0; o < 3; o++) {
                    float w = S.sw[((o * 16 + ic) * 3 + dy) * 3 + dx];
                    acc[0][o] = fmaf(a0, w, acc[0][o]);
                    acc[1][o] = fmaf(a1, w, acc[1][o]);
                    acc[2][o] = fmaf(a2, w, acc[2][o]);
                    acc[3][o] = fmaf(a3, w, acc[3][o]);
                }
            }

    float* ob = out + bidx * 3072;
    #pragma unroll
    for (int p = 0; p < 4; p++) {
        int y = y0 + p * 8;
        #pragma unroll
        for (int o = 0; o < 3; o++) {
            float v = acc[p][o];
            ob[(o << 10) + (y << 5) + xc] = 1.f / (1.f + __expf(-v));
        }
    }
}

// ---------------- launch ----------------
extern "C" void kernel_launch(void* const* d_in, const int* in_sizes, int n_in,
                              void* d_out, int out_size)
{
    const float* x        = (const float*)d_in[0];
    const float* conv1_w  = (const float*)d_in[1];
    const float* conv1_b  = (const float*)d_in[2];
    const float* conv2_w  = (const float*)d_in[3];
    const float* conv2_b  = (const float*)d_in[4];
    const float* fc_w     = (const float*)d_in[5];
    const float* fc_b     = (const float*)d_in[6];
    const float* q_w      = (const float*)d_in[7];
    const float* fc2_w    = (const float*)d_in[8];
    const float* fc2_b    = (const float*)d_in[9];
    const float* dconv1_w = (const float*)d_in[10];
    const float* dconv1_b = (const float*)d_in[11];
    const float* dconv2_w = (const float*)d_in[12];
    const float* dconv2_b = (const float*)d_in[13];
    float* out = (float*)d_out;

    const int batch = in_sizes[0] / (3 * 32 * 32);

    cudaFuncSetAttribute(frontend_kernel, cudaFuncAttributeMaxDynamicSharedMemorySize,
                         (int)sizeof(FrontSmem));
    cudaFuncSetAttribute(backend_kernel, cudaFuncAttributeMaxDynamicSharedMemorySize,
                         (int)sizeof(BackSmem));

    prep_kernel<<<64, 256>>>(fc_w, fc2_w, fc2_b, dconv1_w, dconv1_b);
    frontend_kernel<<<batch, 256, sizeof(FrontSmem)>>>(x, conv1_w, conv1_b,
                                                       conv2_w, conv2_b, fc_b);
    quantum_kernel<<<(batch + 255) / 256, 256>>>(q_w, batch);
    backend_kernel<<<batch, 256, sizeof(BackSmem)>>>(dconv2_w, dconv2_b, out);
}